// round 9
// baseline (speedup 1.0000x reference)
#include <cuda_runtime.h>
#include <cstdint>

// ---------------- problem constants ----------------
#define KNMS 100
#define BMAX 32
#define IOU_THR 0.3f

#define CS13 169
#define CS26 676
#define CS52 2704
#define BASE13 0
#define BASE26 507
#define BASE52 2535
#define LCAP 256            // compact candidate list capacity

__device__ __forceinline__ float sigmoidf_(float x) {
    return 1.0f / (1.0f + expf(-x));
}

// ============================================================
// ONE kernel, one block/image, 1024 threads.
//  1. scores -> 15 REGISTER slots/thread (never shared), pass-0
//     histogram (top byte) fused into the same sweep
//  2. pass-1 histogram (byte 1) -> 16-bit prefix P16 w/ suffix>=100
//  3. compact candidates (top16 >= P16, ~140) into shared list
//  4. exact rank on 64-bit keys (score bits desc, idx asc):
//     rank<100  ==  stable sorted top-100 (no sort, no tie pass)
//  5. gather-decode 100 anchors into rank slot
//  6. suppression-bitmask NMS + pipelined single-thread greedy
// ============================================================
__global__ void __launch_bounds__(1024)
detector_kernel(const float* __restrict__ o13, const float* __restrict__ o26,
                const float* __restrict__ o52, const float* __restrict__ anc,
                const float* __restrict__ thr_p, float* __restrict__ out, int B)
{
    const int b = blockIdx.x;
    const int tid = threadIdx.x;
    const int lane = tid & 31;

    __shared__ unsigned hist[256];
    __shared__ unsigned long long ckey[LCAP];     // compact candidates
    __shared__ unsigned srank[LCAP];
    __shared__ unsigned long long selkey[KNMS];   // top-100, sorted
    __shared__ float sbox[KNMS * 6];
    __shared__ float sarea[KNMS];
    __shared__ unsigned sup[KNMS * 4];
    __shared__ unsigned keep0w[4], keepw[4];
    __shared__ unsigned sh_p0;
    __shared__ int sh_k, sh_cnt;

    const float thr = *thr_p;

    // ---- 1. compute 15 per-thread score slots in registers ----
    unsigned sbits[15];
    {
        const float* b13 = o13 + (size_t)b * 255 * CS13;
        const float* b26 = o26 + (size_t)b * 255 * CS26;
        const float* b52 = o52 + (size_t)b * 255 * CS52;
        #pragma unroll
        for (int a = 0; a < 3; ++a) {
            const float* p13 = b13 + (size_t)a * 85 * CS13;
            const float* p26 = b26 + (size_t)a * 85 * CS26;
            const float* p52 = b52 + (size_t)a * 85 * CS52;
            {
                unsigned r = 0;
                if (tid < CS13) { float c = sigmoidf_(p13[tid]); if (c > thr) r = __float_as_uint(c); }
                sbits[a * 5 + 0] = r;
            }
            {
                unsigned r = 0;
                if (tid < CS26) { float c = sigmoidf_(p26[tid]); if (c > thr) r = __float_as_uint(c); }
                sbits[a * 5 + 1] = r;
            }
            #pragma unroll
            for (int j = 0; j < 3; ++j) {
                unsigned r = 0;
                int cell = j * 1024 + tid;
                if (cell < CS52) { float c = sigmoidf_(p52[cell]); if (c > thr) r = __float_as_uint(c); }
                sbits[a * 5 + 2 + j] = r;
            }
        }
    }
    if (tid < 256) hist[tid] = 0u;
    if (tid < 4) keep0w[tid] = 0u;
    if (tid == 0) { sh_k = KNMS; sh_cnt = 0; }
    __syncthreads();

    // ---- pass 0: histogram of top byte (nonzero scores only) ----
    #pragma unroll
    for (int s = 0; s < 15; ++s) {
        unsigned bits = sbits[s];
        bool act = (bits != 0u);
        unsigned am = __ballot_sync(0xffffffffu, act);
        if (act) {
            unsigned bin = bits >> 24;
            unsigned peers = __match_any_sync(am, bin);
            if (lane == __ffs(peers) - 1)
                atomicAdd(&hist[bin], (unsigned)__popc(peers));
        }
    }
    __syncthreads();

    // warp 0: pick top byte (largest bin w/ suffix >= k), residual k
    if (tid < 32) {
        unsigned c[8];
        int T = 0;
        #pragma unroll
        for (int r = 0; r < 8; ++r) { c[r] = hist[tid * 8 + r]; T += (int)c[r]; }
        int S = T;
        #pragma unroll
        for (int off = 1; off < 32; off <<= 1) {
            int v = __shfl_down_sync(0xffffffffu, S, off);
            if (tid + off < 32) S += v;
        }
        int Snext = __shfl_down_sync(0xffffffffu, S, 1);
        if (tid == 31) Snext = 0;
        int k = KNMS;
        if (S >= k && Snext < k) {
            int rem = Snext, chosen = 0;
            #pragma unroll
            for (int r = 7; r >= 0; --r) {
                if (rem + (int)c[r] >= k) { chosen = r; break; }
                rem += (int)c[r];
            }
            sh_p0 = (unsigned)(tid * 8 + chosen);
            sh_k = k - rem;
        }
    }
    __syncthreads();
    const unsigned p0 = sh_p0;
    const int k1 = sh_k;
    if (tid < 256) hist[tid] = 0u;
    __syncthreads();

    // ---- pass 1: histogram of byte 1 among top-byte == p0 ----
    #pragma unroll
    for (int s = 0; s < 15; ++s) {
        unsigned bits = sbits[s];
        bool act = (bits != 0u) && ((bits >> 24) == p0);
        unsigned am = __ballot_sync(0xffffffffu, act);
        if (act) {
            unsigned bin = (bits >> 16) & 0xFF;
            unsigned peers = __match_any_sync(am, bin);
            if (lane == __ffs(peers) - 1)
                atomicAdd(&hist[bin], (unsigned)__popc(peers));
        }
    }
    __syncthreads();
    if (tid < 32) {
        unsigned c[8];
        int T = 0;
        #pragma unroll
        for (int r = 0; r < 8; ++r) { c[r] = hist[tid * 8 + r]; T += (int)c[r]; }
        int S = T;
        #pragma unroll
        for (int off = 1; off < 32; off <<= 1) {
            int v = __shfl_down_sync(0xffffffffu, S, off);
            if (tid + off < 32) S += v;
        }
        int Snext = __shfl_down_sync(0xffffffffu, S, 1);
        if (tid == 31) Snext = 0;
        if (S >= k1 && Snext < k1) {
            int rem = Snext, chosen = 0;
            #pragma unroll
            for (int r = 7; r >= 0; --r) {
                if (rem + (int)c[r] >= k1) { chosen = r; break; }
                rem += (int)c[r];
            }
            sh_p0 = (p0 << 8) | (unsigned)(tid * 8 + chosen);   // now 16-bit prefix
        }
    }
    if (tid < 256) { ckey[tid] = 0ull; srank[tid] = 0u; }
    __syncthreads();
    const unsigned P16 = sh_p0;

    // ---- 3. compact candidates: top16 >= P16 (>=100 of them, ~140) ----
    #pragma unroll
    for (int s = 0; s < 15; ++s) {
        unsigned bits = sbits[s];
        if (bits != 0u && (bits >> 16) >= P16) {
            // reconstruct anchor index n for this slot
            int a = s / 5, r = s % 5;
            int n;
            if (r == 0)      n = BASE13 + tid * 3 + a;
            else if (r == 1) n = BASE26 + tid * 3 + a;
            else             n = BASE52 + ((r - 2) * 1024 + tid) * 3 + a;
            int pos = atomicAdd(&sh_cnt, 1);
            if (pos < LCAP)
                ckey[pos] = ((unsigned long long)bits << 32) | (unsigned)(~(unsigned)n);
        }
    }
    __syncthreads();

    // ---- 4. exact rank on 64-bit keys (4 slices of 64 per element) ----
    {
        int e = tid >> 2, slice = tid & 3;
        unsigned long long mykey = ckey[e];
        if (mykey != 0ull) {
            int cnt = 0;
            int j0 = slice * 64;
            #pragma unroll 16
            for (int j = 0; j < 64; ++j)
                if (ckey[j0 + j] > mykey) cnt++;
            if (cnt) atomicAdd(&srank[e], (unsigned)cnt);
        }
    }
    __syncthreads();
    if (tid < 256) {
        unsigned long long k = ckey[tid];
        if (k != 0ull) {
            unsigned r = srank[tid];
            if (r < KNMS) selkey[r] = k;       // ranks of real keys are unique
        }
    }
    __syncthreads();

    // ---- 5. gather + decode 100 anchors into their rank slot ----
    {
        int wid = tid >> 5;
        for (int box = wid; box < KNMS; box += 32) {
            unsigned long long key = selkey[box];
            unsigned idx = ~(unsigned)(key & 0xFFFFFFFFu);

            int S, cs, base; float strd; const float* in; const float* arow;
            if (idx < BASE26)      { S = 13; cs = CS13; base = BASE13; strd = 32.f; in = o13; arow = anc + 0; }
            else if (idx < BASE52) { S = 26; cs = CS26; base = BASE26; strd = 16.f; in = o26; arow = anc + 6; }
            else                   { S = 52; cs = CS52; base = BASE52; strd = 8.f;  in = o52; arow = anc + 12; }
            int m = (int)idx - base;
            int cell = m / 3, a = m - cell * 3;
            int y = cell / S, x = cell - y * S;
            const float* p = in + ((size_t)b * 255 + (size_t)a * 85) * cs + cell;

            float v0 = p[(size_t)lane * cs];
            float v1 = p[(size_t)(lane + 32) * cs];
            float v2 = (lane < 21) ? p[(size_t)(lane + 64) * cs] : 0.f;

            float ch0 = __shfl_sync(0xffffffffu, v0, 0);
            float ch1 = __shfl_sync(0xffffffffu, v0, 1);
            float ch2 = __shfl_sync(0xffffffffu, v0, 2);
            float ch3 = __shfl_sync(0xffffffffu, v0, 3);
            float ch4 = __shfl_sync(0xffffffffu, v0, 4);

            // class argmax (first-max wins)
            float bv = -3.402823466e+38f;
            int bi = 0x7FFFFFFF;
            if (lane >= 5)            { bv = v0; bi = lane - 5; }
            if (v1 > bv)              { bv = v1; bi = lane + 27; }
            if (lane < 21 && v2 > bv) { bv = v2; bi = lane + 59; }
            #pragma unroll
            for (int off = 16; off; off >>= 1) {
                float ov = __shfl_xor_sync(0xffffffffu, bv, off);
                int oi = __shfl_xor_sync(0xffffffffu, bi, off);
                if (ov > bv || (ov == bv && oi < bi)) { bv = ov; bi = oi; }
            }

            if (lane == 0) {
                float conf = sigmoidf_(ch0);
                float sx = sigmoidf_(ch1);
                float sy = sigmoidf_(ch2);
                float ww = expf(ch3) * arow[a * 2 + 0];
                float hh = expf(ch4) * arow[a * 2 + 1];
                float ox = ((float)x + sx) * strd;
                float oy = ((float)y + sy) * strd;
                float x1 = ox - 0.5f * ww, y1 = oy - 0.5f * hh;
                float x2 = ox + 0.5f * ww, y2 = oy + 0.5f * hh;
                sbox[box * 6 + 0] = x1;
                sbox[box * 6 + 1] = y1;
                sbox[box * 6 + 2] = x2;
                sbox[box * 6 + 3] = y2;
                sbox[box * 6 + 4] = (float)bi;
                sbox[box * 6 + 5] = conf;
                sarea[box] = fmaxf(x2 - x1, 0.f) * fmaxf(y2 - y1, 0.f);
                if ((unsigned)(key >> 32) != 0u)
                    atomicOr(&keep0w[box >> 5], 1u << (box & 31));
            }
        }
    }
    __syncthreads();

    // ---- 6. suppression masks ----
    for (int w = tid; w < KNMS * 4; w += 1024) {
        int i = w >> 2, c = w & 3;
        unsigned m = 0;
        float ix1 = sbox[i * 6 + 0], iy1 = sbox[i * 6 + 1];
        float ix2 = sbox[i * 6 + 2], iy2 = sbox[i * 6 + 3];
        float icls = sbox[i * 6 + 4], iar = sarea[i];
        int j0 = c * 32;
        #pragma unroll 8
        for (int jj = 0; jj < 32; ++jj) {
            int j = j0 + jj;
            if (j > i && j < KNMS && sbox[j * 6 + 4] == icls) {
                float x1 = fmaxf(ix1, sbox[j * 6 + 0]);
                float y1 = fmaxf(iy1, sbox[j * 6 + 1]);
                float x2 = fminf(ix2, sbox[j * 6 + 2]);
                float y2 = fminf(iy2, sbox[j * 6 + 3]);
                float inter = fmaxf(x2 - x1, 0.f) * fmaxf(y2 - y1, 0.f);
                float uni = iar + sarea[j] - inter;
                if (inter / fmaxf(uni, 1e-9f) > IOU_THR) m |= (1u << jj);
            }
        }
        sup[w] = m;
    }
    __syncthreads();

    // ---- greedy (thread 0), software-pipelined prefetch ----
    if (tid == 0) {
        unsigned k0 = keep0w[0], k1w = keep0w[1], k2 = keep0w[2], k3 = keep0w[3];
        unsigned n0 = sup[0], n1 = sup[1], n2 = sup[2], n3 = sup[3];
        for (int i = 0; i < KNMS; ++i) {
            unsigned s0 = n0, s1 = n1, s2 = n2, s3 = n3;
            if (i + 1 < KNMS) {
                n0 = sup[(i + 1) * 4 + 0];
                n1 = sup[(i + 1) * 4 + 1];
                n2 = sup[(i + 1) * 4 + 2];
                n3 = sup[(i + 1) * 4 + 3];
            }
            unsigned word = (i < 32) ? k0 : (i < 64) ? k1w : (i < 96) ? k2 : k3;
            unsigned msk = (unsigned)(-(int)((word >> (i & 31)) & 1u));
            k0  &= ~(s0 & msk);
            k1w &= ~(s1 & msk);
            k2  &= ~(s2 & msk);
            k3  &= ~(s3 & msk);
        }
        keepw[0] = k0; keepw[1] = k1w; keepw[2] = k2; keepw[3] = k3;
    }
    __syncthreads();

    // ---- write: sel [B,100,6] then keep [B,100] as 0/1 float ----
    float* out_sel = out;
    float* out_keep = out + (size_t)B * KNMS * 6;
    if (tid < KNMS) {
        #pragma unroll
        for (int c = 0; c < 6; ++c)
            out_sel[((size_t)b * KNMS + tid) * 6 + c] = sbox[tid * 6 + c];
        out_keep[(size_t)b * KNMS + tid] =
            ((keepw[tid >> 5] >> (tid & 31)) & 1u) ? 1.0f : 0.0f;
    }
}

// ============================================================
extern "C" void kernel_launch(void* const* d_in, const int* in_sizes, int n_in,
                              void* d_out, int out_size)
{
    const float* o13 = (const float*)d_in[0];
    const float* o26 = (const float*)d_in[1];
    const float* o52 = (const float*)d_in[2];
    const float* anc = (const float*)d_in[3];   // [3,3,2]
    const float* thr = (const float*)d_in[4];   // scalar

    int B = in_sizes[0] / (255 * CS13);
    if (B > BMAX) B = BMAX;
    float* out = (float*)d_out;

    detector_kernel<<<B, 1024>>>(o13, o26, o52, anc, thr, out, B);
}